// round 2
// baseline (speedup 1.0000x reference)
#include <cuda_runtime.h>
#include <cuda_bf16.h>
#include <cstdint>

#define B 8
#define S 2048
#define H 2048
#define A 8192

// output section offsets (element counts, float32)
#define OUT0 0ULL                               // x*best_path  [B*S*H]
#define OUT1 (OUT0 + (size_t)B * S * H)         // new_trails   [H*H]
#define OUT2 (OUT1 + (size_t)H * H)             // new_paths    [A*H]
#define OUT3 (OUT2 + (size_t)A * H)             // new_best_len [1]
#define OUT4 (OUT3 + 1ULL)                      // next_pos     [A] (as f32)

// ---------------- device scratch (no allocations allowed) ----------------
__device__ int   g_next_pos[A];
__device__ float g_len[A];
__device__ float g_diag[H];
__device__ float g_bestpath[H];
__device__ float g_rowmax[H];
__device__ float g_rowlse[H];
__device__ int   g_best_ant;
__device__ int   g_improved;

// ---------------- threefry2x32, key = (0, 42) ----------------
__device__ __forceinline__ void threefry_0_42(uint32_t x0, uint32_t x1,
                                              uint32_t& o0, uint32_t& o1) {
    const uint32_t k0 = 0u, k1 = 42u;
    const uint32_t k2 = k0 ^ k1 ^ 0x1BD11BDAu;
    x0 += k0; x1 += k1;
#define TF_R(r) { x0 += x1; x1 = __funnelshift_l(x1, x1, (r)); x1 ^= x0; }
    TF_R(13) TF_R(15) TF_R(26) TF_R(6)
    x0 += k1; x1 += k2 + 1u;
    TF_R(17) TF_R(29) TF_R(16) TF_R(24)
    x0 += k2; x1 += k0 + 2u;
    TF_R(13) TF_R(15) TF_R(26) TF_R(6)
    x0 += k0; x1 += k1 + 3u;
    TF_R(17) TF_R(29) TF_R(16) TF_R(24)
    x0 += k1; x1 += k2 + 4u;
    TF_R(13) TF_R(15) TF_R(26) TF_R(6)
    x0 += k2; x1 += k0 + 5u;
#undef TF_R
    o0 = x0; o1 = x1;
}

// partitionable threefry 32-bit random bits for flat index i (i < 2^32):
// counter = (hi=0, lo=i), output = out0 ^ out1
__device__ __forceinline__ uint32_t random_bits_partitionable(uint32_t i) {
    uint32_t o0, o1;
    threefry_0_42(0u, i, o0, o1);
    return o0 ^ o1;
}

__device__ __forceinline__ float gumbel_from_bits(uint32_t bits) {
    // JAX uniform(minval=tiny, maxval=1): f in [1,2) -> [0,1)
    float f = __uint_as_float((bits >> 9) | 0x3F800000u) - 1.0f;
    const float tiny = 1.17549435e-38f;
    float u = fmaxf(tiny, f * (1.0f - tiny) + tiny);
    return -logf(-logf(u));
}

// ---------------- K0: per-row max and log-sum-exp of trails; zero diag ----
__global__ void k0_rowstats(const float* __restrict__ trails) {
    __shared__ float sred[256];
    int r = blockIdx.x;
    int tid = threadIdx.x;
    const float* row = trails + (size_t)r * H;
    float m = -__int_as_float(0x7f800000);  // -inf
    #pragma unroll
    for (int k = 0; k < H / 256; k++) m = fmaxf(m, row[tid + k * 256]);
    sred[tid] = m; __syncthreads();
    for (int s = 128; s > 0; s >>= 1) {
        if (tid < s) sred[tid] = fmaxf(sred[tid], sred[tid + s]);
        __syncthreads();
    }
    float rmax = sred[0]; __syncthreads();
    float sum = 0.0f;
    #pragma unroll
    for (int k = 0; k < H / 256; k++) sum += expf(row[tid + k * 256] - rmax);
    sred[tid] = sum; __syncthreads();
    for (int s = 128; s > 0; s >>= 1) {
        if (tid < s) sred[tid] += sred[tid + s];
        __syncthreads();
    }
    if (tid == 0) {
        g_rowmax[r] = rmax;
        g_rowlse[r] = logf(sred[0]);
        g_diag[r]   = 0.0f;
    }
}

// ---------------- K1: categorical sampling, one block per ant --------------
__global__ void k1_nextpos(const float* __restrict__ trails,
                           const int* __restrict__ ant_positions,
                           float* __restrict__ out4) {
    __shared__ float sv[256];
    __shared__ int   si[256];
    int a = blockIdx.x;
    int tid = threadIdx.x;
    int p = ant_positions[a];
    const float* row = trails + (size_t)p * H;
    float rm = g_rowmax[p], rl = g_rowlse[p];

    float bv = -__int_as_float(0x7f800000);
    int   bi = 0;
    #pragma unroll
    for (int k = 0; k < H / 256; k++) {
        int h = k * 256 + tid;                 // coalesced
        uint32_t i = (uint32_t)a * H + (uint32_t)h;
        uint32_t bits = random_bits_partitionable(i);
        float z = gumbel_from_bits(bits) + ((row[h] - rm) - rl);
        if (z > bv) { bv = z; bi = h; }        // h increasing per thread -> first index kept
    }
    sv[tid] = bv; si[tid] = bi; __syncthreads();
    for (int s = 128; s > 0; s >>= 1) {
        if (tid < s) {
            float v2 = sv[tid + s]; int i2 = si[tid + s];
            if (v2 > sv[tid] || (v2 == sv[tid] && i2 < si[tid])) { sv[tid] = v2; si[tid] = i2; }
        }
        __syncthreads();
    }
    if (tid == 0) { g_next_pos[a] = si[0]; out4[a] = (float)si[0]; }
}

// ---------------- K2: new_paths, path lengths, diag scatter ----------------
__global__ void k2_paths(const float* __restrict__ ant_paths,
                         const float* __restrict__ strength_p,
                         float* __restrict__ out2) {
    __shared__ float sred[256];
    __shared__ float s_update;
    int a = blockIdx.x;
    int tid = threadIdx.x;
    int np = g_next_pos[a];
    const float* row = ant_paths + (size_t)a * H;
    float v[H / 256];
    float sum = 0.0f;
    #pragma unroll
    for (int k = 0; k < H / 256; k++) {
        int h = k * 256 + tid;
        float t = row[h];
        if (h == np) t = 1.0f;
        v[k] = t;
        sum += t * t;
    }
    sred[tid] = sum; __syncthreads();
    for (int s = 128; s > 0; s >>= 1) {
        if (tid < s) sred[tid] += sred[tid + s];
        __syncthreads();
    }
    if (tid == 0) {
        float len = sqrtf(sred[0]);
        g_len[a] = len;
        s_update = strength_p[0] / (len + 1e-8f);
    }
    __syncthreads();
    float upd = s_update;
    #pragma unroll
    for (int k = 0; k < H / 256; k++) {
        int h = k * 256 + tid;
        out2[(size_t)a * H + h] = v[k];
        if (v[k] > 0.0f) atomicAdd(&g_diag[h], upd);
    }
}

// ---------------- K3: argmin of path lengths, best-length output -----------
__global__ void k3_best(const float* __restrict__ bpl_p,
                        float* __restrict__ out3) {
    __shared__ float sv[256];
    __shared__ int   si[256];
    int tid = threadIdx.x;
    float bv = __int_as_float(0x7f800000); int bi = 0;  // +inf
    for (int a = tid; a < A; a += 256) {
        float v = g_len[a];
        if (v < bv) { bv = v; bi = a; }   // ascending a => first index kept
    }
    sv[tid] = bv; si[tid] = bi; __syncthreads();
    for (int s = 128; s > 0; s >>= 1) {
        if (tid < s) {
            float v2 = sv[tid + s]; int i2 = si[tid + s];
            if (v2 < sv[tid] || (v2 == sv[tid] && i2 < si[tid])) { sv[tid] = v2; si[tid] = i2; }
        }
        __syncthreads();
    }
    if (tid == 0) {
        float bpl = bpl_p[0];
        int improved = sv[0] < bpl;
        g_best_ant = si[0];
        g_improved = improved;
        out3[0] = improved ? sv[0] : bpl;
    }
}

// ---------------- K4: materialize best path vector -------------------------
__global__ void k4_bestpath(const float* __restrict__ best_path_in,
                            const float* __restrict__ new_paths_out) {
    int h = blockIdx.x * blockDim.x + threadIdx.x;
    if (h < H) {
        g_bestpath[h] = g_improved ? new_paths_out[(size_t)g_best_ant * H + h]
                                   : best_path_in[h];
    }
}

// ---------------- K5: trails update ----------------------------------------
__global__ void k5_trails(const float* __restrict__ trails,
                          const float* __restrict__ decay_p,
                          float* __restrict__ out1) {
    size_t gid = (size_t)blockIdx.x * blockDim.x + threadIdx.x;
    size_t idx4 = gid * 4;
    if (idx4 >= (size_t)H * H) return;
    int i = (int)(idx4 / H);
    int j0 = (int)(idx4 % H);
    float dec = 1.0f - decay_p[0];
    const float4 t = *reinterpret_cast<const float4*>(trails + idx4);
    float d = g_diag[i];
    float4 o;
    o.x = (t.x + (i == (j0 + 0) ? d : 0.0f)) * dec;
    o.y = (t.y + (i == (j0 + 1) ? d : 0.0f)) * dec;
    o.z = (t.z + (i == (j0 + 2) ? d : 0.0f)) * dec;
    o.w = (t.w + (i == (j0 + 3) ? d : 0.0f)) * dec;
    *reinterpret_cast<float4*>(out1 + idx4) = o;
}

// ---------------- K6: output = x * best_path broadcast ---------------------
__global__ void k6_output(const float* __restrict__ x,
                          float* __restrict__ out0) {
    size_t gid = (size_t)blockIdx.x * blockDim.x + threadIdx.x;
    size_t idx4 = gid * 4;
    if (idx4 >= (size_t)B * S * H) return;
    int h0 = (int)(idx4 & (H - 1));
    const float4 xv = *reinterpret_cast<const float4*>(x + idx4);
    float4 o;
    o.x = xv.x * g_bestpath[h0 + 0];
    o.y = xv.y * g_bestpath[h0 + 1];
    o.z = xv.z * g_bestpath[h0 + 2];
    o.w = xv.w * g_bestpath[h0 + 3];
    *reinterpret_cast<float4*>(out0 + idx4) = o;
}

extern "C" void kernel_launch(void* const* d_in, const int* in_sizes, int n_in,
                              void* d_out, int out_size) {
    const float* x        = (const float*)d_in[0];
    const float* trails   = (const float*)d_in[1];
    const float* paths    = (const float*)d_in[2];
    const float* bestpath = (const float*)d_in[3];
    const float* bpl      = (const float*)d_in[4];
    const float* decay    = (const float*)d_in[5];
    const float* strength = (const float*)d_in[6];
    const int*   antpos   = (const int*)d_in[7];
    float* out = (float*)d_out;

    k0_rowstats<<<H, 256>>>(trails);
    k1_nextpos<<<A, 256>>>(trails, antpos, out + OUT4);
    k2_paths<<<A, 256>>>(paths, strength, out + OUT2);
    k3_best<<<1, 256>>>(bpl, out + OUT3);
    k4_bestpath<<<(H + 255) / 256, 256>>>(bestpath, out + OUT2);
    k5_trails<<<(H * H / 4 + 255) / 256, 256>>>(trails, decay, out + OUT1);
    k6_output<<<((size_t)B * S * H / 4 + 255) / 256, 256>>>(x, out + OUT0);
}

// round 3
// speedup vs baseline: 1.2699x; 1.2699x over previous
#include <cuda_runtime.h>
#include <cuda_bf16.h>
#include <cstdint>

#define B 8
#define S 2048
#define H 2048
#define A 8192

// output section offsets (element counts, float32)
#define OUT0 0ULL                               // x*best_path  [B*S*H]
#define OUT1 (OUT0 + (size_t)B * S * H)         // new_trails   [H*H]
#define OUT2 (OUT1 + (size_t)H * H)             // new_paths    [A*H]
#define OUT3 (OUT2 + (size_t)A * H)             // new_best_len [1]
#define OUT4 (OUT3 + 1ULL)                      // next_pos     [A] (as f32)

#define TRAIL_BLOCKS (H * H / 4 / 256)          // 4096
#define OUT_BLOCKS   ((B * S * H) / 4 / 256)    // 32768

// ---------------- device scratch (no allocations allowed) ----------------
__device__ float g_len[A];
__device__ float g_diag[H];
__device__ float g_bestpath[H];
__device__ float g_rowmax[H];
__device__ float g_rowlse[H];

// ---------------- threefry2x32, key = (0, 42) ----------------
__device__ __forceinline__ void threefry_0_42(uint32_t x0, uint32_t x1,
                                              uint32_t& o0, uint32_t& o1) {
    const uint32_t k0 = 0u, k1 = 42u;
    const uint32_t k2 = k0 ^ k1 ^ 0x1BD11BDAu;
    x0 += k0; x1 += k1;
#define TF_R(r) { x0 += x1; x1 = __funnelshift_l(x1, x1, (r)); x1 ^= x0; }
    TF_R(13) TF_R(15) TF_R(26) TF_R(6)
    x0 += k1; x1 += k2 + 1u;
    TF_R(17) TF_R(29) TF_R(16) TF_R(24)
    x0 += k2; x1 += k0 + 2u;
    TF_R(13) TF_R(15) TF_R(26) TF_R(6)
    x0 += k0; x1 += k1 + 3u;
    TF_R(17) TF_R(29) TF_R(16) TF_R(24)
    x0 += k1; x1 += k2 + 4u;
    TF_R(13) TF_R(15) TF_R(26) TF_R(6)
    x0 += k2; x1 += k0 + 5u;
#undef TF_R
    o0 = x0; o1 = x1;
}

// partitionable threefry: counter = (0, i), bits = out0 ^ out1
__device__ __forceinline__ uint32_t random_bits_partitionable(uint32_t i) {
    uint32_t o0, o1;
    threefry_0_42(0u, i, o0, o1);
    return o0 ^ o1;
}

__device__ __forceinline__ float gumbel_from_bits(uint32_t bits) {
    float f = __uint_as_float((bits >> 9) | 0x3F800000u) - 1.0f;
    const float tiny = 1.17549435e-38f;
    float u = fmaxf(tiny, f * (1.0f - tiny) + tiny);
    // fast log: ordering-only use (gumbel values never reach the output)
    float t = -__logf(u);
    return -__logf(t);
}

// ---------------- K0: per-row max and log-sum-exp of trails; zero diag ----
__global__ void k0_rowstats(const float* __restrict__ trails) {
    __shared__ float sred[256];
    int r = blockIdx.x;
    int tid = threadIdx.x;
    const float* row = trails + (size_t)r * H;
    float m = -__int_as_float(0x7f800000);
    #pragma unroll
    for (int k = 0; k < H / 256; k++) m = fmaxf(m, row[tid + k * 256]);
    sred[tid] = m; __syncthreads();
    for (int s = 128; s > 0; s >>= 1) {
        if (tid < s) sred[tid] = fmaxf(sred[tid], sred[tid + s]);
        __syncthreads();
    }
    float rmax = sred[0]; __syncthreads();
    float sum = 0.0f;
    #pragma unroll
    for (int k = 0; k < H / 256; k++) sum += expf(row[tid + k * 256] - rmax);
    sred[tid] = sum; __syncthreads();
    for (int s = 128; s > 0; s >>= 1) {
        if (tid < s) sred[tid] += sred[tid + s];
        __syncthreads();
    }
    if (tid == 0) {
        g_rowmax[r] = rmax;
        g_rowlse[r] = logf(sred[0]);
        g_diag[r]   = 0.0f;
    }
}

// ---------------- K12: fused sampling + paths + lengths + diag -------------
__global__ void k12_sample_paths(const float* __restrict__ trails,
                                 const float* __restrict__ ant_paths,
                                 const int* __restrict__ ant_positions,
                                 const float* __restrict__ strength_p,
                                 float* __restrict__ out2,
                                 float* __restrict__ out4) {
    __shared__ float sv[256];
    __shared__ int   si[256];
    __shared__ float ss[256];
    __shared__ float s_upd;
    __shared__ int   s_np;
    int a = blockIdx.x;
    int tid = threadIdx.x;
    int p = ant_positions[a];
    const float* trow = trails + (size_t)p * H;
    const float* prow = ant_paths + (size_t)a * H;
    float rm = g_rowmax[p], rl = g_rowlse[p];

    // loop1: gumbel-argmax (ALU heavy) + ant_paths sumsq (memory, hidden)
    float bv = -__int_as_float(0x7f800000);
    int   bi = 0;
    float sumsq = 0.0f;
    #pragma unroll
    for (int k = 0; k < H / 256; k++) {
        int h = k * 256 + tid;
        uint32_t i = (uint32_t)a * H + (uint32_t)h;
        uint32_t bits = random_bits_partitionable(i);
        float z = gumbel_from_bits(bits) + ((trow[h] - rm) - rl);
        if (z > bv) { bv = z; bi = h; }      // h increasing -> first index kept
        float pv = prow[h];
        sumsq += pv * pv;
    }
    sv[tid] = bv; si[tid] = bi; ss[tid] = sumsq; __syncthreads();
    for (int s = 128; s > 0; s >>= 1) {
        if (tid < s) {
            float v2 = sv[tid + s]; int i2 = si[tid + s];
            if (v2 > sv[tid] || (v2 == sv[tid] && i2 < si[tid])) { sv[tid] = v2; si[tid] = i2; }
            ss[tid] += ss[tid + s];
        }
        __syncthreads();
    }
    if (tid == 0) {
        int np = si[0];
        float old = prow[np];
        float len = sqrtf(ss[0] - old * old + 1.0f);   // one-hot substitution
        g_len[a] = len;
        s_np = np;
        s_upd = strength_p[0] / (len + 1e-8f);
        out4[a] = (float)np;
    }
    __syncthreads();
    int np = s_np;
    float upd = s_upd;
    // loop2: write new_paths (row re-read hits L2) + diag scatter
    #pragma unroll
    for (int k = 0; k < H / 256; k++) {
        int h = k * 256 + tid;
        float v = prow[h];
        if (h == np) v = 1.0f;
        out2[(size_t)a * H + h] = v;
        if (v > 0.0f) atomicAdd(&g_diag[h], upd);
    }
}

// ---------------- K34: argmin + best path materialization (1 block) --------
__global__ void k34_best(const float* __restrict__ bpl_p,
                         const float* __restrict__ best_path_in,
                         const float* __restrict__ new_paths_out,
                         float* __restrict__ out3) {
    __shared__ float sv[1024];
    __shared__ int   si[1024];
    __shared__ int   s_best, s_imp;
    int tid = threadIdx.x;
    float bv = __int_as_float(0x7f800000); int bi = 0;
    for (int a = tid; a < A; a += 1024) {
        float v = g_len[a];
        if (v < bv) { bv = v; bi = a; }     // ascending a => first index kept
    }
    sv[tid] = bv; si[tid] = bi; __syncthreads();
    for (int s = 512; s > 0; s >>= 1) {
        if (tid < s) {
            float v2 = sv[tid + s]; int i2 = si[tid + s];
            if (v2 < sv[tid] || (v2 == sv[tid] && i2 < si[tid])) { sv[tid] = v2; si[tid] = i2; }
        }
        __syncthreads();
    }
    if (tid == 0) {
        float bpl = bpl_p[0];
        int improved = sv[0] < bpl;
        s_best = si[0];
        s_imp = improved;
        out3[0] = improved ? sv[0] : bpl;
    }
    __syncthreads();
    int best = s_best, imp = s_imp;
    for (int h = tid; h < H; h += 1024) {
        g_bestpath[h] = imp ? new_paths_out[(size_t)best * H + h] : best_path_in[h];
    }
}

// ---------------- K56: trails update + broadcast multiply (one launch) -----
__global__ void k56_finish(const float* __restrict__ trails,
                           const float* __restrict__ decay_p,
                           const float* __restrict__ x,
                           float* __restrict__ out1,
                           float* __restrict__ out0) {
    int b = blockIdx.x;
    int tid = threadIdx.x;
    if (b < TRAIL_BLOCKS) {
        size_t idx4 = ((size_t)b * 256 + tid) * 4;
        int i  = (int)(idx4 >> 11);       // row
        int j0 = (int)(idx4 & (H - 1));
        float dec = 1.0f - decay_p[0];
        const float4 t = *reinterpret_cast<const float4*>(trails + idx4);
        float d = g_diag[i];
        float4 o;
        o.x = (t.x + (i == (j0 + 0) ? d : 0.0f)) * dec;
        o.y = (t.y + (i == (j0 + 1) ? d : 0.0f)) * dec;
        o.z = (t.z + (i == (j0 + 2) ? d : 0.0f)) * dec;
        o.w = (t.w + (i == (j0 + 3) ? d : 0.0f)) * dec;
        *reinterpret_cast<float4*>(out1 + idx4) = o;
    } else {
        size_t idx4 = ((size_t)(b - TRAIL_BLOCKS) * 256 + tid) * 4;
        int h0 = (int)(idx4 & (H - 1));
        const float4 xv = *reinterpret_cast<const float4*>(x + idx4);
        float4 o;
        o.x = xv.x * g_bestpath[h0 + 0];
        o.y = xv.y * g_bestpath[h0 + 1];
        o.z = xv.z * g_bestpath[h0 + 2];
        o.w = xv.w * g_bestpath[h0 + 3];
        *reinterpret_cast<float4*>(out0 + idx4) = o;
    }
}

extern "C" void kernel_launch(void* const* d_in, const int* in_sizes, int n_in,
                              void* d_out, int out_size) {
    const float* x        = (const float*)d_in[0];
    const float* trails   = (const float*)d_in[1];
    const float* paths    = (const float*)d_in[2];
    const float* bestpath = (const float*)d_in[3];
    const float* bpl      = (const float*)d_in[4];
    const float* decay    = (const float*)d_in[5];
    const float* strength = (const float*)d_in[6];
    const int*   antpos   = (const int*)d_in[7];
    float* out = (float*)d_out;

    k0_rowstats<<<H, 256>>>(trails);
    k12_sample_paths<<<A, 256>>>(trails, paths, antpos, strength,
                                 out + OUT2, out + OUT4);
    k34_best<<<1, 1024>>>(bpl, bestpath, out + OUT2, out + OUT3);
    k56_finish<<<TRAIL_BLOCKS + OUT_BLOCKS, 256>>>(trails, decay, x,
                                                   out + OUT1, out + OUT0);
}

// round 4
// speedup vs baseline: 1.3378x; 1.0535x over previous
#include <cuda_runtime.h>
#include <cuda_bf16.h>
#include <cstdint>

#define B 8
#define S 2048
#define H 2048
#define A 8192

// output section offsets (element counts, float32)
#define OUT0 0ULL                               // x*best_path  [B*S*H]
#define OUT1 (OUT0 + (size_t)B * S * H)         // new_trails   [H*H]
#define OUT2 (OUT1 + (size_t)H * H)             // new_paths    [A*H]
#define OUT3 (OUT2 + (size_t)A * H)             // new_best_len [1]
#define OUT4 (OUT3 + 1ULL)                      // next_pos     [A] (as f32)

#define TRAIL_BLOCKS (H * H / 4 / 256)              // 4096
#define OUT_BLOCKS   ((B * S * H) / 4 / 256 / 2)    // 16384 (2 float4 per thread)

// ---------------- device scratch (no allocations allowed) ----------------
__device__ float g_len[A];
__device__ float g_diag[H];
__device__ float g_bestpath[H];
__device__ float g_rowmax[H];
__device__ float g_rowlse[H];
__device__ int   g_rowconst[H];

// ---------------- threefry2x32, key = (0, 42) ----------------
__device__ __forceinline__ void threefry_0_42(uint32_t x0, uint32_t x1,
                                              uint32_t& o0, uint32_t& o1) {
    const uint32_t k0 = 0u, k1 = 42u;
    const uint32_t k2 = k0 ^ k1 ^ 0x1BD11BDAu;
    x0 += k0; x1 += k1;
#define TF_R(r) { x0 += x1; x1 = __funnelshift_l(x1, x1, (r)); x1 ^= x0; }
    TF_R(13) TF_R(15) TF_R(26) TF_R(6)
    x0 += k1; x1 += k2 + 1u;
    TF_R(17) TF_R(29) TF_R(16) TF_R(24)
    x0 += k2; x1 += k0 + 2u;
    TF_R(13) TF_R(15) TF_R(26) TF_R(6)
    x0 += k0; x1 += k1 + 3u;
    TF_R(17) TF_R(29) TF_R(16) TF_R(24)
    x0 += k1; x1 += k2 + 4u;
    TF_R(13) TF_R(15) TF_R(26) TF_R(6)
    x0 += k2; x1 += k0 + 5u;
#undef TF_R
    o0 = x0; o1 = x1;
}

// partitionable threefry: counter = (0, i), bits = out0 ^ out1
__device__ __forceinline__ uint32_t random_bits_partitionable(uint32_t i) {
    uint32_t o0, o1;
    threefry_0_42(0u, i, o0, o1);
    return o0 ^ o1;
}

__device__ __forceinline__ float gumbel_from_bits(uint32_t bits) {
    float f = __uint_as_float((bits >> 9) | 0x3F800000u) - 1.0f;
    const float tiny = 1.17549435e-38f;
    float u = fmaxf(tiny, f * (1.0f - tiny) + tiny);
    float t = -__logf(u);
    return -__logf(t);
}

// ---------------- K0: row max/lse/const-flag of trails; zero diag ----------
__global__ void k0_rowstats(const float* __restrict__ trails) {
    __shared__ float smax[256];
    __shared__ float smin[256];
    int r = blockIdx.x;
    int tid = threadIdx.x;
    const float* row = trails + (size_t)r * H;
    float m = -__int_as_float(0x7f800000);
    float mn = __int_as_float(0x7f800000);
    #pragma unroll
    for (int k = 0; k < H / 256; k++) {
        float v = row[tid + k * 256];
        m = fmaxf(m, v); mn = fminf(mn, v);
    }
    smax[tid] = m; smin[tid] = mn; __syncthreads();
    for (int s = 128; s > 0; s >>= 1) {
        if (tid < s) {
            smax[tid] = fmaxf(smax[tid], smax[tid + s]);
            smin[tid] = fminf(smin[tid], smin[tid + s]);
        }
        __syncthreads();
    }
    float rmax = smax[0], rmin = smin[0]; __syncthreads();
    float sum = 0.0f;
    #pragma unroll
    for (int k = 0; k < H / 256; k++) sum += expf(row[tid + k * 256] - rmax);
    smax[tid] = sum; __syncthreads();
    for (int s = 128; s > 0; s >>= 1) {
        if (tid < s) smax[tid] += smax[tid + s];
        __syncthreads();
    }
    if (tid == 0) {
        g_rowmax[r] = rmax;
        g_rowlse[r] = logf(smax[0]);
        g_rowconst[r] = (rmax == rmin);
        g_diag[r] = 0.0f;
    }
}

// ---------------- K12: fused sampling + paths + lengths + diag -------------
__global__ void k12_sample_paths(const float* __restrict__ trails,
                                 const float* __restrict__ ant_paths,
                                 const int* __restrict__ ant_positions,
                                 const float* __restrict__ strength_p,
                                 float* __restrict__ out2,
                                 float* __restrict__ out4) {
    __shared__ float sv[256];
    __shared__ int   si[256];
    __shared__ float ss[256];
    __shared__ float s_upd;
    __shared__ int   s_np;
    int a = blockIdx.x;
    int tid = threadIdx.x;
    int p = ant_positions[a];
    const float* prow = ant_paths + (size_t)a * H;

    float v[H / 256];
    float bv = -__int_as_float(0x7f800000);
    int   bi = 0;
    float sumsq = 0.0f;

    if (g_rowconst[p]) {
        // constant logits: argmax z == argmax u == argmax (bits>>9).
        // 23-bit value -> exact float conversion preserves order AND ties.
        #pragma unroll
        for (int k = 0; k < H / 256; k++) {
            int h = k * 256 + tid;
            uint32_t bits = random_bits_partitionable((uint32_t)a * H + (uint32_t)h);
            float z = (float)(bits >> 9);
            if (z > bv) { bv = z; bi = h; }   // h increasing -> first index kept
            float pv = prow[h];
            v[k] = pv;
            sumsq += pv * pv;
        }
    } else {
        const float* trow = trails + (size_t)p * H;
        float rm = g_rowmax[p], rl = g_rowlse[p];
        #pragma unroll
        for (int k = 0; k < H / 256; k++) {
            int h = k * 256 + tid;
            uint32_t bits = random_bits_partitionable((uint32_t)a * H + (uint32_t)h);
            float z = gumbel_from_bits(bits) + ((trow[h] - rm) - rl);
            if (z > bv) { bv = z; bi = h; }
            float pv = prow[h];
            v[k] = pv;
            sumsq += pv * pv;
        }
    }

    sv[tid] = bv; si[tid] = bi; ss[tid] = sumsq; __syncthreads();
    for (int s = 128; s > 0; s >>= 1) {
        if (tid < s) {
            float v2 = sv[tid + s]; int i2 = si[tid + s];
            if (v2 > sv[tid] || (v2 == sv[tid] && i2 < si[tid])) { sv[tid] = v2; si[tid] = i2; }
            ss[tid] += ss[tid + s];
        }
        __syncthreads();
    }
    if (tid == 0) {
        int np = si[0];
        float old = prow[np];
        float len = sqrtf(ss[0] - old * old + 1.0f);   // one-hot substitution
        g_len[a] = len;
        s_np = np;
        s_upd = strength_p[0] / (len + 1e-8f);
        out4[a] = (float)np;
    }
    __syncthreads();
    int np = s_np;
    float upd = s_upd;
    // loop2: write new_paths from registers + diag scatter
    #pragma unroll
    for (int k = 0; k < H / 256; k++) {
        int h = k * 256 + tid;
        float pv = v[k];
        if (h == np) pv = 1.0f;
        out2[(size_t)a * H + h] = pv;
        if (pv > 0.0f) atomicAdd(&g_diag[h], upd);
    }
}

// ---------------- K34: argmin + best path materialization (1 block) --------
__global__ void k34_best(const float* __restrict__ bpl_p,
                         const float* __restrict__ best_path_in,
                         const float* __restrict__ new_paths_out,
                         float* __restrict__ out3) {
    __shared__ float sv[1024];
    __shared__ int   si[1024];
    __shared__ int   s_best, s_imp;
    int tid = threadIdx.x;
    float bv = __int_as_float(0x7f800000); int bi = 0;
    for (int a = tid; a < A; a += 1024) {
        float v = g_len[a];
        if (v < bv) { bv = v; bi = a; }     // ascending a => first index kept
    }
    sv[tid] = bv; si[tid] = bi; __syncthreads();
    for (int s = 512; s > 0; s >>= 1) {
        if (tid < s) {
            float v2 = sv[tid + s]; int i2 = si[tid + s];
            if (v2 < sv[tid] || (v2 == sv[tid] && i2 < si[tid])) { sv[tid] = v2; si[tid] = i2; }
        }
        __syncthreads();
    }
    if (tid == 0) {
        float bpl = bpl_p[0];
        int improved = sv[0] < bpl;
        s_best = si[0];
        s_imp = improved;
        out3[0] = improved ? sv[0] : bpl;
    }
    __syncthreads();
    int best = s_best, imp = s_imp;
    for (int h = tid; h < H; h += 1024) {
        g_bestpath[h] = imp ? new_paths_out[(size_t)best * H + h] : best_path_in[h];
    }
}

// ---------------- K56: trails update + broadcast multiply (one launch) -----
__global__ void k56_finish(const float* __restrict__ trails,
                           const float* __restrict__ decay_p,
                           const float* __restrict__ x,
                           float* __restrict__ out1,
                           float* __restrict__ out0) {
    int b = blockIdx.x;
    int tid = threadIdx.x;
    if (b < TRAIL_BLOCKS) {
        size_t idx4 = ((size_t)b * 256 + tid) * 4;
        int i  = (int)(idx4 >> 11);       // row
        int j0 = (int)(idx4 & (H - 1));
        float dec = 1.0f - decay_p[0];
        const float4 t = *reinterpret_cast<const float4*>(trails + idx4);
        float d = g_diag[i];
        float4 o;
        o.x = (t.x + (i == (j0 + 0) ? d : 0.0f)) * dec;
        o.y = (t.y + (i == (j0 + 1) ? d : 0.0f)) * dec;
        o.z = (t.z + (i == (j0 + 2) ? d : 0.0f)) * dec;
        o.w = (t.w + (i == (j0 + 3) ? d : 0.0f)) * dec;
        *reinterpret_cast<float4*>(out1 + idx4) = o;
    } else {
        // output section: 2 independent float4 per thread for MLP
        size_t base = (size_t)(b - TRAIL_BLOCKS) * 256 + tid;
        size_t idxA = base * 4;
        size_t idxB = (base + (size_t)OUT_BLOCKS * 256) * 4;
        const float4 xa = *reinterpret_cast<const float4*>(x + idxA);
        const float4 xb = *reinterpret_cast<const float4*>(x + idxB);
        int hA = (int)(idxA & (H - 1));
        int hB = (int)(idxB & (H - 1));
        float4 oa, ob;
        oa.x = xa.x * g_bestpath[hA + 0];
        oa.y = xa.y * g_bestpath[hA + 1];
        oa.z = xa.z * g_bestpath[hA + 2];
        oa.w = xa.w * g_bestpath[hA + 3];
        ob.x = xb.x * g_bestpath[hB + 0];
        ob.y = xb.y * g_bestpath[hB + 1];
        ob.z = xb.z * g_bestpath[hB + 2];
        ob.w = xb.w * g_bestpath[hB + 3];
        *reinterpret_cast<float4*>(out0 + idxA) = oa;
        *reinterpret_cast<float4*>(out0 + idxB) = ob;
    }
}

extern "C" void kernel_launch(void* const* d_in, const int* in_sizes, int n_in,
                              void* d_out, int out_size) {
    const float* x        = (const float*)d_in[0];
    const float* trails   = (const float*)d_in[1];
    const float* paths    = (const float*)d_in[2];
    const float* bestpath = (const float*)d_in[3];
    const float* bpl      = (const float*)d_in[4];
    const float* decay    = (const float*)d_in[5];
    const float* strength = (const float*)d_in[6];
    const int*   antpos   = (const int*)d_in[7];
    float* out = (float*)d_out;

    k0_rowstats<<<H, 256>>>(trails);
    k12_sample_paths<<<A, 256>>>(trails, paths, antpos, strength,
                                 out + OUT2, out + OUT4);
    k34_best<<<1, 1024>>>(bpl, bestpath, out + OUT2, out + OUT3);
    k56_finish<<<TRAIL_BLOCKS + OUT_BLOCKS, 256>>>(trails, decay, x,
                                                   out + OUT1, out + OUT0);
}